// round 2
// baseline (speedup 1.0000x reference)
#include <cuda_runtime.h>

// Problem constants
#define Bq 32
#define Nq 512
#define Fq 64
#define Tq 24
#define Kq 3
#define Oq 64
#define OT 1536           // O*T
#define KM 1536           // K*N (contraction dim of stage B)
#define BNOT 25165824     // B*N*O*T

// Scratch (static device globals: allowed; no runtime allocation)
__device__ float g_A[(size_t)Bq * Kq * Nq * Nq];        // 25,165,824 floats (softmaxed attention)
__device__ float g_U[(size_t)Bq * Kq * Nq * Oq * Tq];   // 75,497,472 floats (projected x)
__device__ float g_M[Fq * Kq * Oq];                     // [F][K*O]  composed projection

// ---------------------------------------------------------------------------
// FMA-only exp (keeps 25M exps off the MUFU pipe). exp(x)=2^(x*log2e) via
// magic-constant round + degree-5 poly. Softmax domain x<=0; clamped.
// ---------------------------------------------------------------------------
__device__ __forceinline__ float fast_exp(float x) {
    x = fminf(fmaxf(x, -87.0f), 0.0f);
    const float L2E = 1.4426950408889634f;
    float t  = fmaf(x, L2E, 12582912.0f);     // round(x*log2e) via magic
    float fi = t - 12582912.0f;               // integer part as float
    float f  = fmaf(x, L2E, -fi);             // fraction in [-0.5, 0.5]
    int   i  = __float_as_int(t) - 0x4B400000;
    float p  = 1.3333558146428443e-3f;
    p = fmaf(p, f, 9.6181291076284772e-3f);
    p = fmaf(p, f, 5.5504108664821580e-2f);
    p = fmaf(p, f, 2.4022650695910072e-1f);
    p = fmaf(p, f, 6.9314718055994531e-1f);
    p = fmaf(p, f, 1.0f);
    return __int_as_float((i + 127) << 23) * p;
}

// ---------------------------------------------------------------------------
// Kernel 0: M[k,f,o] = sum_{op} theta[k,f,op] * W[op*K + k, o]
// stored as g_M[f*192 + k*64 + o]
// ---------------------------------------------------------------------------
__global__ void k_computeM(const float* __restrict__ theta, const float* __restrict__ W) {
    int idx = blockIdx.x * blockDim.x + threadIdx.x;
    if (idx >= Kq * Fq * Oq) return;
    int o = idx & 63;
    int f = (idx >> 6) & 63;
    int k = idx >> 12;
    const float* th = theta + ((size_t)k * Fq + f) * Oq;
    float acc = 0.f;
#pragma unroll 8
    for (int op = 0; op < Oq; ++op)
        acc = fmaf(th[op], W[((size_t)op * Kq + k) * Oq + o], acc);
    g_M[f * (Kq * Oq) + k * Oq + o] = acc;
}

// ---------------------------------------------------------------------------
// Kernel 1: row softmax of spatial_attention -> g_A. One warp per 512-row,
// whole row in registers, FMA-only exp.
// ---------------------------------------------------------------------------
__global__ void __launch_bounds__(256) k_softmax(const float* __restrict__ sa) {
    int row  = blockIdx.x * 8 + (threadIdx.x >> 5);   // B*K*N = 49152 rows
    int lane = threadIdx.x & 31;
    const float4* src = (const float4*)sa + (size_t)row * 128;
    float4 v[4];
#pragma unroll
    for (int i = 0; i < 4; i++) v[i] = src[i * 32 + lane];

    float mx = v[0].x;
#pragma unroll
    for (int i = 0; i < 4; i++)
        mx = fmaxf(mx, fmaxf(fmaxf(v[i].x, v[i].y), fmaxf(v[i].z, v[i].w)));
#pragma unroll
    for (int off = 16; off > 0; off >>= 1)
        mx = fmaxf(mx, __shfl_xor_sync(0xffffffffu, mx, off));

    float s = 0.f;
#pragma unroll
    for (int i = 0; i < 4; i++) {
        v[i].x = fast_exp(v[i].x - mx); s += v[i].x;
        v[i].y = fast_exp(v[i].y - mx); s += v[i].y;
        v[i].z = fast_exp(v[i].z - mx); s += v[i].z;
        v[i].w = fast_exp(v[i].w - mx); s += v[i].w;
    }
#pragma unroll
    for (int off = 16; off > 0; off >>= 1)
        s += __shfl_xor_sync(0xffffffffu, s, off);
    float inv = 1.0f / s;

    float4* dst = (float4*)g_A + (size_t)row * 128;
#pragma unroll
    for (int i = 0; i < 4; i++) {
        v[i].x *= inv; v[i].y *= inv; v[i].z *= inv; v[i].w *= inv;
        dst[i * 32 + lane] = v[i];
    }
}

// ---------------------------------------------------------------------------
// Kernel 2 (stage A): u[b,k,m,o,t] = sum_f M[k,f,o] * x[b,m,f,t]
// One block = (b, 4 consecutive m, k). 128 threads; per-thread 4(o) x 12(t)
// register tile -> 4 LDS.128 per 48 FFMA per f step (FMA-bound).
// ---------------------------------------------------------------------------
__global__ void __launch_bounds__(128) k_stageA(const float* __restrict__ x) {
    __shared__ float Ms[Fq * 64];       // [f][o] slice for this k   (16 KB)
    __shared__ float xs[4 * Fq * Tq];   // 4 m-rows of x             (24 KB)

    int bx = blockIdx.x;
    int k  = bx % 3;
    int mq = (bx / 3) & 127;
    int b  = bx / 384;
    int m0 = mq * 4;
    int tid = threadIdx.x;

    {   // Stage M slice [64 f][64 o] from g_M[f*192 + k*64 + o]
        const float* src = g_M + k * 64;
        float4* Md = (float4*)Ms;
        for (int i = tid; i < Fq * 16; i += 128) {
            int f = i >> 4, c = i & 15;
            Md[i] = *(const float4*)(src + f * 192 + c * 4);
        }
    }
    {   // Stage x rows m0..m0+3 (contiguous 6144 floats)
        const float4* xg = (const float4*)(x + ((size_t)b * Nq + m0) * (Fq * Tq));
        float4* xd = (float4*)xs;
        for (int i = tid; i < 1536; i += 128) xd[i] = xg[i];
    }
    __syncthreads();

    int mi = tid >> 5;            // warp -> m index
    int r  = tid & 31;
    int ob = (r >> 1) * 4;        // o base (0..60 step 4)
    int tb = (r & 1) * 12;        // t base (0 or 12)
    const float* xr = xs + mi * (Fq * Tq);

    float acc[4][12];
#pragma unroll
    for (int i = 0; i < 4; i++)
#pragma unroll
        for (int j = 0; j < 12; j++) acc[i][j] = 0.f;

#pragma unroll 8
    for (int f = 0; f < Fq; ++f) {
        float4 a4 = *(const float4*)(Ms + f * 64 + ob);
        float4 x0 = *(const float4*)(xr + f * Tq + tb);
        float4 x1 = *(const float4*)(xr + f * Tq + tb + 4);
        float4 x2 = *(const float4*)(xr + f * Tq + tb + 8);
        float ar[4]  = {a4.x, a4.y, a4.z, a4.w};
        float xv[12] = {x0.x, x0.y, x0.z, x0.w, x1.x, x1.y, x1.z, x1.w,
                        x2.x, x2.y, x2.z, x2.w};
#pragma unroll
        for (int oi = 0; oi < 4; ++oi)
#pragma unroll
            for (int ti = 0; ti < 12; ++ti)
                acc[oi][ti] = fmaf(ar[oi], xv[ti], acc[oi][ti]);
    }

    float* ub = g_U + (((size_t)b * Kq + k) * Nq + m0 + mi) * OT + ob * Tq + tb;
#pragma unroll
    for (int oi = 0; oi < 4; ++oi)
#pragma unroll
        for (int c = 0; c < 3; ++c)
            *(float4*)(ub + oi * Tq + c * 4) =
                make_float4(acc[oi][c*4], acc[oi][c*4+1], acc[oi][c*4+2], acc[oi][c*4+3]);
}

// ---------------------------------------------------------------------------
// Kernel 3 (stage B): per b: C[n,j] = sum_p A[p,n] * U[p,j], p=(k,m), j=(o,t)
// y[b,n,:,:] = tanh(C + bias[j/24]). 128x128x16 SGEMM, 8x8/thread, register
// prefetch, fused epilogue writes y directly (C layout == y[b] slice layout).
// ---------------------------------------------------------------------------
__global__ void __launch_bounds__(256, 2) k_stageB(const float* __restrict__ bias,
                                                   float* __restrict__ y) {
    __shared__ float As[16][128];
    __shared__ float Us[16][128];
    __shared__ float bs[64];

    int tid = threadIdx.x;
    int jt = blockIdx.x, nt = blockIdx.y, b = blockIdx.z;
    const float* Ab = g_A + (size_t)b * KM * Nq + nt * 128;
    const float* Ub = g_U + (size_t)b * KM * OT + jt * 128;
    if (tid < 64) bs[tid] = bias[tid];

    int row0 = tid >> 5;            // 0..7
    int col  = (tid & 31) * 4;      // 0..124

    float4 pa0 = *(const float4*)(Ab + (size_t)row0 * Nq + col);
    float4 pa1 = *(const float4*)(Ab + (size_t)(row0 + 8) * Nq + col);
    float4 pu0 = *(const float4*)(Ub + (size_t)row0 * OT + col);
    float4 pu1 = *(const float4*)(Ub + (size_t)(row0 + 8) * OT + col);

    float acc[8][8];
#pragma unroll
    for (int i = 0; i < 8; i++)
#pragma unroll
        for (int j = 0; j < 8; j++) acc[i][j] = 0.f;

    int tx = tid & 15, ty = tid >> 4;
    const int NIT = KM / 16;   // 96

    for (int it = 0; it < NIT; ++it) {
        *(float4*)&As[row0][col]     = pa0;
        *(float4*)&As[row0 + 8][col] = pa1;
        *(float4*)&Us[row0][col]     = pu0;
        *(float4*)&Us[row0 + 8][col] = pu1;
        __syncthreads();

        if (it + 1 < NIT) {
            const float* An = Ab + (size_t)(it + 1) * 16 * Nq;
            const float* Un = Ub + (size_t)(it + 1) * 16 * OT;
            pa0 = *(const float4*)(An + (size_t)row0 * Nq + col);
            pa1 = *(const float4*)(An + (size_t)(row0 + 8) * Nq + col);
            pu0 = *(const float4*)(Un + (size_t)row0 * OT + col);
            pu1 = *(const float4*)(Un + (size_t)(row0 + 8) * OT + col);
        }

#pragma unroll
        for (int p = 0; p < 16; ++p) {
            float4 a0 = *(const float4*)&As[p][ty * 4];
            float4 a1 = *(const float4*)&As[p][64 + ty * 4];
            float4 u0 = *(const float4*)&Us[p][tx * 4];
            float4 u1 = *(const float4*)&Us[p][64 + tx * 4];
            float ar[8] = {a0.x, a0.y, a0.z, a0.w, a1.x, a1.y, a1.z, a1.w};
            float ur[8] = {u0.x, u0.y, u0.z, u0.w, u1.x, u1.y, u1.z, u1.w};
#pragma unroll
            for (int i = 0; i < 8; i++)
#pragma unroll
                for (int j = 0; j < 8; j++)
                    acc[i][j] = fmaf(ar[i], ur[j], acc[i][j]);
        }
        __syncthreads();
    }

    // Epilogue: y[b,n,j] = tanh(C + bias[j/24]); y slice layout == C layout
    float* yb = y + (size_t)b * Nq * OT + (size_t)nt * 128 * OT + jt * 128;
    int jg0 = jt * 128;
#pragma unroll
    for (int rh = 0; rh < 2; ++rh) {
#pragma unroll
        for (int i = 0; i < 4; ++i) {
            int nl = rh * 64 + ty * 4 + i;
#pragma unroll
            for (int ch = 0; ch < 2; ++ch) {
                int jl = ch * 64 + tx * 4;
                const float* a = &acc[rh * 4 + i][ch * 4];
                float4 v;
                v.x = tanhf(a[0] + bs[(jg0 + jl + 0) / 24]);
                v.y = tanhf(a[1] + bs[(jg0 + jl + 1) / 24]);
                v.z = tanhf(a[2] + bs[(jg0 + jl + 2) / 24]);
                v.w = tanhf(a[3] + bs[(jg0 + jl + 3) / 24]);
                *(float4*)(yb + (size_t)nl * OT + jl) = v;
            }
        }
    }
}

// Zero the tail of d_out (the scalar kl = 0, if the harness packs it)
__global__ void k_zero_tail(float* __restrict__ out, int n) {
    int i = blockIdx.x * blockDim.x + threadIdx.x;
    if (i < n) out[BNOT + i] = 0.f;
}

// ---------------------------------------------------------------------------
extern "C" void kernel_launch(void* const* d_in, const int* in_sizes, int n_in,
                              void* d_out, int out_size) {
    const float* x     = (const float*)d_in[0];   // [B,N,F,T]
    const float* sa    = (const float*)d_in[1];   // [B,K,N,N]
    const float* theta = (const float*)d_in[2];   // [K,F,O]
    const float* W     = (const float*)d_in[3];   // [K*O,O]
    const float* bias  = (const float*)d_in[4];   // [O]
    float* y = (float*)d_out;

    k_computeM<<<48, 256>>>(theta, W);
    k_softmax<<<6144, 256>>>(sa);                 // 49152 rows / 8 per block
    k_stageA<<<Bq * 128 * 3, 128>>>(x);           // (b, m-quad, k)
    dim3 g3(12, 4, Bq);                           // (j-tiles, n-tiles, b)
    k_stageB<<<g3, 256>>>(bias, y);

    int tail = out_size - BNOT;
    if (tail > 0)
        k_zero_tail<<<(tail + 255) / 256, 256>>>(y, tail);
}

// round 4
// speedup vs baseline: 1.1074x; 1.1074x over previous
#include <cuda_runtime.h>
#include <cuda_bf16.h>

// Problem constants
#define Bq 32
#define Nq 512
#define Fq 64
#define Tq 24
#define Kq 3
#define Oq 64
#define OT 1536           // O*T
#define KM 1536           // K*N (contraction dim of stage B)
#define BNOT 25165824     // B*N*O*T

// Scratch: split bf16 operands, pre-transposed K-major.
// g_A*[b][n][p], g_U*[b][j][p], p = k*512 + m.
__device__ __nv_bfloat16 g_Ah[(size_t)Bq * Nq * KM];
__device__ __nv_bfloat16 g_Al[(size_t)Bq * Nq * KM];
__device__ __nv_bfloat16 g_Uh[(size_t)Bq * OT * KM];
__device__ __nv_bfloat16 g_Ul[(size_t)Bq * OT * KM];
__device__ float g_M[Fq * Kq * Oq];     // [f][k*64+o] composed projection

// ===========================================================================
// PTX helpers (base sm_100: mma.sync + ldmatrix + cp.async only)
// ===========================================================================
__device__ __forceinline__ unsigned smem_u32(const void* p) {
    unsigned a;
    asm("{ .reg .u64 t; cvta.to.shared.u64 t, %1; cvt.u32.u64 %0, t; }"
        : "=r"(a) : "l"(p));
    return a;
}
#define SW128(x) ((x) ^ (((x) >> 3) & 0x70))
#define CPA(dst, src) \
    asm volatile("cp.async.cg.shared.global [%0], [%1], 16;" :: "r"(dst), "l"(src))

__device__ __forceinline__ void ldsm4(unsigned* r, unsigned addr) {
    asm volatile("ldmatrix.sync.aligned.m8n8.x4.shared.b16 {%0,%1,%2,%3}, [%4];"
                 : "=r"(r[0]), "=r"(r[1]), "=r"(r[2]), "=r"(r[3]) : "r"(addr));
}
__device__ __forceinline__ void mma16816(float* c, const unsigned* a, const unsigned* b) {
    asm volatile(
        "mma.sync.aligned.m16n8k16.row.col.f32.bf16.bf16.f32 "
        "{%0,%1,%2,%3}, {%4,%5,%6,%7}, {%8,%9}, {%0,%1,%2,%3};"
        : "+f"(c[0]), "+f"(c[1]), "+f"(c[2]), "+f"(c[3])
        : "r"(a[0]), "r"(a[1]), "r"(a[2]), "r"(a[3]), "r"(b[0]), "r"(b[1]));
}

// ===========================================================================
// FMA-only exp (keeps 25M exps off MUFU). Softmax domain x<=0.
// ===========================================================================
__device__ __forceinline__ float fast_exp(float x) {
    x = fminf(fmaxf(x, -87.0f), 0.0f);
    const float L2E = 1.4426950408889634f;
    float t  = fmaf(x, L2E, 12582912.0f);
    float fi = t - 12582912.0f;
    float f  = fmaf(x, L2E, -fi);
    int   i  = __float_as_int(t) - 0x4B400000;
    float p  = 1.3333558146428443e-3f;
    p = fmaf(p, f, 9.6181291076284772e-3f);
    p = fmaf(p, f, 5.5504108664821580e-2f);
    p = fmaf(p, f, 2.4022650695910072e-1f);
    p = fmaf(p, f, 6.9314718055994531e-1f);
    p = fmaf(p, f, 1.0f);
    return __int_as_float((i + 127) << 23) * p;
}

__device__ __forceinline__ unsigned pack_bf2(__nv_bfloat16 a, __nv_bfloat16 b) {
    return (unsigned)__bfloat16_as_ushort(a) |
           ((unsigned)__bfloat16_as_ushort(b) << 16);
}

// ===========================================================================
// Kernel 0: M[k,f,o] = sum_{op} theta[k,f,op] * W[op*K+k, o] -> g_M[f*192+k*64+o]
// ===========================================================================
__global__ void k_computeM(const float* __restrict__ theta, const float* __restrict__ W) {
    int idx = blockIdx.x * blockDim.x + threadIdx.x;
    if (idx >= Kq * Fq * Oq) return;
    int o = idx & 63;
    int f = (idx >> 6) & 63;
    int k = idx >> 12;
    const float* th = theta + ((size_t)k * Fq + f) * Oq;
    float acc = 0.f;
#pragma unroll 8
    for (int op = 0; op < Oq; ++op)
        acc = fmaf(th[op], W[((size_t)op * Kq + k) * Oq + o], acc);
    g_M[f * (Kq * Oq) + k * Oq + o] = acc;
}

// ===========================================================================
// Kernel 1: softmax + transpose + bf16 hi/lo split.
// Block = (b, k, 16 m-rows). Warp computes 4 rows; smem transpose; writeout
// [n][m0..m0+15] as 32B hi + 32B lo stores.
// ===========================================================================
__global__ void __launch_bounds__(128) k_softmax_t(const float* __restrict__ sa) {
    __shared__ float srow[16][513];
    int bx = blockIdx.x;
    int k = bx % 3, mt = (bx / 3) & 31, b = bx / 96;
    int m0 = mt * 16;
    int tid = threadIdx.x, w = tid >> 5, lane = tid & 31;

#pragma unroll
    for (int i = 0; i < 4; ++i) {
        int ml = w * 4 + i;
        const float4* src =
            (const float4*)(sa + (((size_t)(b * 3 + k) * Nq + m0 + ml) * Nq));
        float4 v[4];
#pragma unroll
        for (int q = 0; q < 4; ++q) v[q] = src[q * 32 + lane];

        float mx = v[0].x;
#pragma unroll
        for (int q = 0; q < 4; ++q)
            mx = fmaxf(mx, fmaxf(fmaxf(v[q].x, v[q].y), fmaxf(v[q].z, v[q].w)));
#pragma unroll
        for (int off = 16; off > 0; off >>= 1)
            mx = fmaxf(mx, __shfl_xor_sync(0xffffffffu, mx, off));

        float s = 0.f;
#pragma unroll
        for (int q = 0; q < 4; ++q) {
            v[q].x = fast_exp(v[q].x - mx); s += v[q].x;
            v[q].y = fast_exp(v[q].y - mx); s += v[q].y;
            v[q].z = fast_exp(v[q].z - mx); s += v[q].z;
            v[q].w = fast_exp(v[q].w - mx); s += v[q].w;
        }
#pragma unroll
        for (int off = 16; off > 0; off >>= 1)
            s += __shfl_xor_sync(0xffffffffu, s, off);
        float inv = 1.0f / s;

#pragma unroll
        for (int q = 0; q < 4; ++q) {
            int n = (q * 32 + lane) * 4;
            srow[ml][n + 0] = v[q].x * inv;
            srow[ml][n + 1] = v[q].y * inv;
            srow[ml][n + 2] = v[q].z * inv;
            srow[ml][n + 3] = v[q].w * inv;
        }
    }
    __syncthreads();

#pragma unroll
    for (int q = 0; q < 4; ++q) {
        int n = tid + q * 128;
        unsigned hw[8], lw[8];
#pragma unroll
        for (int mm = 0; mm < 8; ++mm) {
            float f0 = srow[2 * mm][n], f1 = srow[2 * mm + 1][n];
            __nv_bfloat16 h0 = __float2bfloat16(f0);
            __nv_bfloat16 h1 = __float2bfloat16(f1);
            __nv_bfloat16 l0 = __float2bfloat16(f0 - __bfloat162float(h0));
            __nv_bfloat16 l1 = __float2bfloat16(f1 - __bfloat162float(h1));
            hw[mm] = pack_bf2(h0, h1);
            lw[mm] = pack_bf2(l0, l1);
        }
        size_t base = ((size_t)b * Nq + n) * KM + k * Nq + m0;
        uint4* ph = (uint4*)(g_Ah + base);
        ph[0] = make_uint4(hw[0], hw[1], hw[2], hw[3]);
        ph[1] = make_uint4(hw[4], hw[5], hw[6], hw[7]);
        uint4* pl = (uint4*)(g_Al + base);
        pl[0] = make_uint4(lw[0], lw[1], lw[2], lw[3]);
        pl[1] = make_uint4(lw[4], lw[5], lw[6], lw[7]);
    }
}

// ===========================================================================
// Kernel 2 (stage A): u[j][p] = sum_f M[k][f][o] * x[b][m][f][t], transposed +
// split to bf16 hi/lo. Block = (b, k, 16 m). 512 threads (warp <-> m), each
// lane a 4(o) x 12(t) register tile; smem-staged transposed writeout.
// Dynamic smem: Ms 16KB | xs 96KB | st 48KB = 160KB.
// ===========================================================================
__global__ void __launch_bounds__(512) k_stageA_t(const float* __restrict__ x) {
    extern __shared__ float dsa[];
    float* Ms = dsa;                       // 4096 floats
    float* xs = dsa + 4096;                // 24576 floats
    __nv_bfloat16* st = (__nv_bfloat16*)(dsa + 4096 + 24576);  // 24576 bf16

    int bx = blockIdx.x;
    int k = bx % 3, mt = (bx / 3) & 31, b = bx / 96;
    int m0 = mt * 16;
    int tid = threadIdx.x;

    {   // M slice [64 f][64 o]
        const float* src = g_M + k * 64;
        float4* Md = (float4*)Ms;
        for (int i = tid; i < Fq * 16; i += 512) {
            int f = i >> 4, c = i & 15;
            Md[i] = *(const float4*)(src + f * 192 + c * 4);
        }
    }
    {   // x rows m0..m0+15 (contiguous 24576 floats)
        const float4* xg = (const float4*)(x + ((size_t)b * Nq + m0) * (Fq * Tq));
        float4* xd = (float4*)xs;
        for (int i = tid; i < 6144; i += 512) xd[i] = xg[i];
    }
    __syncthreads();

    int mi = tid >> 5;
    int r = tid & 31;
    int ob = (r >> 1) * 4;
    int tb = (r & 1) * 12;
    const float* xr = xs + mi * (Fq * Tq);

    float acc[4][12];
#pragma unroll
    for (int i = 0; i < 4; i++)
#pragma unroll
        for (int j = 0; j < 12; j++) acc[i][j] = 0.f;

#pragma unroll 8
    for (int f = 0; f < Fq; ++f) {
        float4 a4 = *(const float4*)(Ms + f * 64 + ob);
        float4 x0 = *(const float4*)(xr + f * Tq + tb);
        float4 x1 = *(const float4*)(xr + f * Tq + tb + 4);
        float4 x2 = *(const float4*)(xr + f * Tq + tb + 8);
        float ar[4]  = {a4.x, a4.y, a4.z, a4.w};
        float xv[12] = {x0.x, x0.y, x0.z, x0.w, x1.x, x1.y, x1.z, x1.w,
                        x2.x, x2.y, x2.z, x2.w};
#pragma unroll
        for (int oi = 0; oi < 4; ++oi)
#pragma unroll
            for (int ti = 0; ti < 12; ++ti)
                acc[oi][ti] = fmaf(ar[oi], xv[ti], acc[oi][ti]);
    }

    // round 1: hi
#pragma unroll
    for (int oi = 0; oi < 4; ++oi)
#pragma unroll
        for (int c = 0; c < 12; ++c) {
            int j = (ob + oi) * Tq + tb + c;
            st[j * 16 + mi] = __float2bfloat16(acc[oi][c]);
        }
    __syncthreads();
#pragma unroll
    for (int q = 0; q < 3; ++q) {
        int j = tid + q * 512;
        uint4 v0 = *(uint4*)(st + j * 16);
        uint4 v1 = *(uint4*)(st + j * 16 + 8);
        size_t o = ((size_t)b * OT + j) * KM + k * Nq + m0;
        *(uint4*)(g_Uh + o) = v0;
        *(uint4*)(g_Uh + o + 8) = v1;
    }
    __syncthreads();

    // round 2: lo
#pragma unroll
    for (int oi = 0; oi < 4; ++oi)
#pragma unroll
        for (int c = 0; c < 12; ++c) {
            int j = (ob + oi) * Tq + tb + c;
            float h = __bfloat162float(__float2bfloat16(acc[oi][c]));
            st[j * 16 + mi] = __float2bfloat16(acc[oi][c] - h);
        }
    __syncthreads();
#pragma unroll
    for (int q = 0; q < 3; ++q) {
        int j = tid + q * 512;
        uint4 v0 = *(uint4*)(st + j * 16);
        uint4 v1 = *(uint4*)(st + j * 16 + 8);
        size_t o = ((size_t)b * OT + j) * KM + k * Nq + m0;
        *(uint4*)(g_Ul + o) = v0;
        *(uint4*)(g_Ul + o + 8) = v1;
    }
}

// ===========================================================================
// Kernel 3 (stage B): split-bf16 GEMM via mma.sync (HMMA, base sm_100).
// CTA tile 128(n) x 128(j); 8 warps, warp tile 64x32 (m16n8k16 frags 4x4).
// C = Ah*Uh + Ah*Ul + Al*Uh  (Al*Ul dropped, ~2^-16 rel).
// K-chunks of 64, double-buffered cp.async (SW128 swizzle), fused bias+tanh.
// ===========================================================================
#define CHUNKS 24
#define BUFSZ 65536        // 4 tiles x 16KB (Ah, Al, Uh, Ul) per chunk
#define SMEM_B_REQ (2 * BUFSZ + 1024)

__global__ void __launch_bounds__(256) k_stageB_mma(const float* __restrict__ bias,
                                                    float* __restrict__ y) {
    extern __shared__ char dsm[];
    unsigned raw = smem_u32(dsm);
    unsigned S0 = (raw + 1023u) & ~1023u;

    int tid = threadIdx.x;
    int w = tid >> 5, lane = tid & 31;
    int wm = w & 1, wn = w >> 1;          // warp: m-half (64), j-quarter (32)
    int jt = blockIdx.x, nt = blockIdx.y, b = blockIdx.z;

    const __nv_bfloat16* pAh = g_Ah + ((size_t)b * Nq + nt * 128) * KM;
    const __nv_bfloat16* pAl = g_Al + ((size_t)b * Nq + nt * 128) * KM;
    const __nv_bfloat16* pUh = g_Uh + ((size_t)b * OT + jt * 128) * KM;
    const __nv_bfloat16* pUl = g_Ul + ((size_t)b * OT + jt * 128) * KM;

    // ldmatrix per-lane address components
    int sub = lane >> 3, l7 = lane & 7;
    int rowA = (sub & 1) * 8 + l7;  int kA = (sub >> 1) * 16;   // A: m-blocks then k-halves
    int rowU = (sub >> 1) * 8 + l7; int kU = (sub & 1) * 16;    // B: k-halves then n-blocks

    float acc[4][4][4];
#pragma unroll
    for (int i = 0; i < 4; i++)
#pragma unroll
        for (int j = 0; j < 4; j++)
#pragma unroll
            for (int c = 0; c < 4; c++) acc[i][j][c] = 0.f;

    // chunk fill: 4 tiles of 128 rows x 64 bf16 (128B rows), SW128 swizzled
    auto fill = [&](int ch) {
        unsigned bb = S0 + (ch & 1) * BUFSZ;
        size_t cofs = (size_t)ch * 64;
#pragma unroll
        for (int l = 0; l < 4; ++l) {
            int idx = tid + l * 256;
            int rr = idx >> 3, cc = idx & 7;
            unsigned so = SW128(rr * 128 + cc * 16);
            size_t g = (size_t)rr * KM + cofs + cc * 8;
            CPA(bb + 0     + so, pAh + g);
            CPA(bb + 16384 + so, pAl + g);
            CPA(bb + 32768 + so, pUh + g);
            CPA(bb + 49152 + so, pUl + g);
        }
        asm volatile("cp.async.commit_group;");
    };

    fill(0);
    for (int ch = 0; ch < CHUNKS; ++ch) {
        if (ch + 1 < CHUNKS) {
            fill(ch + 1);
            asm volatile("cp.async.wait_group 1;" ::: "memory");
        } else {
            asm volatile("cp.async.wait_group 0;" ::: "memory");
        }
        __syncthreads();

        unsigned bb = S0 + (ch & 1) * BUFSZ;
        unsigned AhB = bb, AlB = bb + 16384, UhB = bb + 32768, UlB = bb + 49152;
#pragma unroll
        for (int ks = 0; ks < 4; ++ks) {
            unsigned ah[4][4], al[4][4], uh[2][4], ul[2][4];
#pragma unroll
            for (int mf = 0; mf < 4; ++mf) {
                unsigned so = SW128((unsigned)((wm * 64 + mf * 16 + rowA) * 128 + ks * 32 + kA));
                ldsm4(ah[mf], AhB + so);
                ldsm4(al[mf], AlB + so);
            }
#pragma unroll
            for (int nfp = 0; nfp < 2; ++nfp) {
                unsigned so = SW128((unsigned)((wn * 32 + nfp * 16 + rowU) * 128 + ks * 32 + kU));
                ldsm4(uh[nfp], UhB + so);
                ldsm4(ul[nfp], UlB + so);
            }
#pragma unroll
            for (int mf = 0; mf < 4; ++mf)
#pragma unroll
                for (int nf = 0; nf < 4; ++nf) {
                    const unsigned* bh = &uh[nf >> 1][(nf & 1) * 2];
                    const unsigned* bl = &ul[nf >> 1][(nf & 1) * 2];
                    mma16816(acc[mf][nf], ah[mf], bh);
                    mma16816(acc[mf][nf], ah[mf], bl);
                    mma16816(acc[mf][nf], al[mf], bh);
                }
        }
        __syncthreads();   // protect buffer before next fill overwrites it
    }

    // Epilogue: C frag (m16n8): c0,c1 -> (row gid, cols 2tig,2tig+1); c2,c3 -> row gid+8
    int gid = lane >> 2, tig = lane & 3;
#pragma unroll
    for (int mf = 0; mf < 4; ++mf) {
        int nrow = nt * 128 + wm * 64 + mf * 16 + gid;
        float* y0 = y + ((size_t)b * Nq + nrow) * OT + jt * 128;
        float* y1 = y0 + 8 * OT;
#pragma unroll
        for (int nf = 0; nf < 4; ++nf) {
            int jl = wn * 32 + nf * 8 + 2 * tig;
            int jg = jt * 128 + jl;
            float b0 = __ldg(&bias[jg / 24]);
            float b1 = __ldg(&bias[(jg + 1) / 24]);
            float2 v0, v1;
            v0.x = tanhf(acc[mf][nf][0] + b0);
            v0.y = tanhf(acc[mf][nf][1] + b1);
            v1.x = tanhf(acc[mf][nf][2] + b0);
            v1.y = tanhf(acc[mf][nf][3] + b1);
            *(float2*)(y0 + jl) = v0;
            *(float2*)(y1 + jl) = v1;
        }
    }
}

// Zero the tail of d_out (kl scalar), if present
__global__ void k_zero_tail(float* __restrict__ out, int n) {
    int i = blockIdx.x * blockDim.x + threadIdx.x;
    if (i < n) out[BNOT + i] = 0.f;
}

// ===========================================================================
extern "C" void kernel_launch(void* const* d_in, const int* in_sizes, int n_in,
                              void* d_out, int out_size) {
    const float* x     = (const float*)d_in[0];   // [B,N,F,T]
    const float* sa    = (const float*)d_in[1];   // [B,K,N,N]
    const float* theta = (const float*)d_in[2];   // [K,F,O]
    const float* W     = (const float*)d_in[3];   // [K*O,O]
    const float* bias  = (const float*)d_in[4];   // [O]
    float* y = (float*)d_out;

    cudaFuncSetAttribute(k_stageA_t, cudaFuncAttributeMaxDynamicSharedMemorySize, 163840);
    cudaFuncSetAttribute(k_stageB_mma, cudaFuncAttributeMaxDynamicSharedMemorySize, SMEM_B_REQ);

    k_computeM<<<48, 256>>>(theta, W);
    k_softmax_t<<<Bq * 32 * 3, 128>>>(sa);            // (b, mt, k) 16-row blocks
    k_stageA_t<<<Bq * 32 * 3, 512, 163840>>>(x);      // (b, mt, k) 16-row blocks
    dim3 gB(12, 4, Bq);                               // (jt, nt, b)
    k_stageB_mma<<<gB, 256, SMEM_B_REQ>>>(bias, y);

    int tail = out_size - BNOT;
    if (tail > 0)
        k_zero_tail<<<(tail + 255) / 256, 256>>>(y, tail);
}